// round 3
// baseline (speedup 1.0000x reference)
#include <cuda_runtime.h>
#include <math.h>

#define NN 100000
#define NE 1600000
#define NB 64
#define FI 16
#define HD 128
#define GF 8
#define F19 19
#define F20 20
#define BN_EPS 1e-5f

// ---------------- scratch (device globals: allocation-free) ----------------
__device__ float g_x19 [NN * F20];
__device__ float g_xa19[NN * F20];
__device__ float g_h   [NN * HD];
__device__ float g_xagg[NN * HD];
__device__ float g_xA  [NN * HD];
__device__ float g_xB  [NN * HD];
__device__ float g_stats[2 * HD];
__device__ float g_coef [2 * HD];
__device__ int   g_gstart[NB + 1];
__device__ float g_pooled[NB * 2 * HD];

// ---------------- helpers ----------------
__device__ __forceinline__ void red_add_v4(float* p, float4 v) {
    asm volatile("red.global.add.v4.f32 [%0], {%1,%2,%3,%4};"
                 :: "l"(p), "f"(v.x), "f"(v.y), "f"(v.z), "f"(v.w) : "memory");
}

__device__ __forceinline__ float elu01(float v) {
    return v > 0.f ? v : 0.1f * expm1f(v);
}

// ---------------- kernels ----------------

// concat h0 (16) + coord0 (3) into padded [N,20] rows; duplicate into xa19
__global__ void k_concat(const float* __restrict__ h0, const float* __restrict__ coord) {
    int i = blockIdx.x * blockDim.x + threadIdx.x;
    if (i >= NN * F20) return;
    int n = i / F20, j = i - n * F20;
    float v = 0.f;
    if (j < FI)        v = h0[n * FI + j];
    else if (j < F19)  v = coord[n * 3 + (j - FI)];
    g_x19[i] = v;
    g_xa19[i] = v;
}

// edge scatter-add for the 20-col (padded) first layer
__global__ void k_scatter19(const int* __restrict__ src, const int* __restrict__ dst) {
    int t = blockIdx.x * blockDim.x + threadIdx.x;
    if (t >= NE * 5) return;
    int e = t / 5, c = (t - e * 5) * 4;
    int s = src[e], d = dst[e];
    float4 v = *(const float4*)&g_x19[s * F20 + c];
    red_add_v4(&g_xa19[d * F20 + c], v);
}

// edge scatter-add for H=128 layers
__global__ void k_scatterH(const float* __restrict__ x, float* __restrict__ xa,
                           const int* __restrict__ src, const int* __restrict__ dst) {
    int t = blockIdx.x * blockDim.x + threadIdx.x;
    if (t >= NE * 32) return;
    int e = t >> 5, c = (t & 31) << 2;
    int s = src[e], d = dst[e];
    float4 v = *(const float4*)&x[s * HD + c];
    red_add_v4(&xa[d * HD + c], v);
}

__global__ void k_copy4(const float4* __restrict__ in, float4* __restrict__ out, int n4) {
    int i = blockIdx.x * blockDim.x + threadIdx.x;
    if (i < n4) out[i] = in[i];
}

__global__ void k_zerostats() { g_stats[threadIdx.x] = 0.f; }  // <<<1,256>>>

// Tiled SGEMM: out[M,128] = A[M,K] @ W[K,128] + bias
//  TRANS_A: apply per-k BN coef + relu to A elements on load (reads g_coef)
//  STATS  : accumulate column sums / sumsq of the (pre-activation) output into g_stats
//  ELU    : apply elu01 to the output
template <bool TRANS_A, bool STATS, bool ELU>
__global__ void k_gemm(const float* __restrict__ A, int lda, int K,
                       const float* __restrict__ W, const float* __restrict__ bias,
                       float* __restrict__ out) {
    __shared__ float As[16][64];
    __shared__ float Bs[16][128];
    __shared__ float s_sum[128];
    __shared__ float s_sq[128];

    const int tid = threadIdx.x;
    const int tx = tid & 15, ty = tid >> 4;
    const int m0 = blockIdx.x * 64;

    float acc[4][8];
#pragma unroll
    for (int r = 0; r < 4; r++)
#pragma unroll
        for (int c = 0; c < 8; c++) acc[r][c] = 0.f;

    for (int k0 = 0; k0 < K; k0 += 16) {
        // load A tile (transposed into As[k][m])
        int ka = k0 + (tid & 15);
        float ta = 0.f, tb = 0.f;
        if (TRANS_A && ka < K) { ta = g_coef[ka]; tb = g_coef[128 + ka]; }
#pragma unroll
        for (int p = 0; p < 4; p++) {
            int m = p * 16 + (tid >> 4);
            int row = m0 + m;
            float v = 0.f;
            if (row < NN && ka < K) {
                v = A[row * lda + ka];
                if (TRANS_A) v = fmaxf(ta * v + tb, 0.f);
            }
            As[tid & 15][m] = v;
        }
        // load W tile
#pragma unroll
        for (int p = 0; p < 8; p++) {
            int idx = p * 256 + tid;
            int kk = idx >> 7, n = idx & 127;
            Bs[kk][n] = (k0 + kk < K) ? W[(k0 + kk) * HD + n] : 0.f;
        }
        __syncthreads();
#pragma unroll
        for (int k = 0; k < 16; k++) {
            float4 a4 = *(const float4*)&As[k][ty * 4];
            float4 b0 = *(const float4*)&Bs[k][tx * 8];
            float4 b1 = *(const float4*)&Bs[k][tx * 8 + 4];
            float av[4] = {a4.x, a4.y, a4.z, a4.w};
            float bv[8] = {b0.x, b0.y, b0.z, b0.w, b1.x, b1.y, b1.z, b1.w};
#pragma unroll
            for (int r = 0; r < 4; r++)
#pragma unroll
                for (int c = 0; c < 8; c++) acc[r][c] += av[r] * bv[c];
        }
        __syncthreads();
    }

    if (STATS) {
        if (tid < 128) { s_sum[tid] = 0.f; s_sq[tid] = 0.f; }
        __syncthreads();
    }

#pragma unroll
    for (int r = 0; r < 4; r++) {
        int row = m0 + ty * 4 + r;
        if (row < NN) {
#pragma unroll
            for (int c = 0; c < 8; c++) {
                int col = tx * 8 + c;
                float v = acc[r][c] + bias[col];
                if (ELU) v = elu01(v);
                out[row * HD + col] = v;
                if (STATS) {
                    atomicAdd(&s_sum[col], v);
                    atomicAdd(&s_sq[col], v * v);
                }
            }
        }
    }
    if (STATS) {
        __syncthreads();
        if (tid < 128) {
            atomicAdd(&g_stats[tid], s_sum[tid]);
            atomicAdd(&g_stats[128 + tid], s_sq[tid]);
        }
    }
}

// turn column sums into BN scale/shift: val*a + b, relu applied later in GEMM
__global__ void k_bncoef(const float* __restrict__ gm, const float* __restrict__ bt) {
    int c = threadIdx.x;  // <<<1,128>>>
    float mean = g_stats[c] * (1.f / NN);
    float var = g_stats[128 + c] * (1.f / NN) - mean * mean;
    float a = gm[c] * rsqrtf(var + BN_EPS);
    g_coef[c] = a;
    g_coef[128 + c] = bt[c] - mean * a;
}

// batch is sorted -> compute per-graph row ranges
__global__ void k_bounds(const int* __restrict__ batch) {
    int i = blockIdx.x * blockDim.x + threadIdx.x;
    if (i >= NN) return;
    int cur = batch[i];
    int prev = (i == 0) ? -1 : batch[i - 1];
    for (int g = prev + 1; g <= cur; ++g) g_gstart[g] = i;
    if (i == NN - 1)
        for (int g = cur + 1; g <= NB; ++g) g_gstart[g] = NN;
}

// per-graph mean + max pooling: one block per graph, 4 row-groups x 128 cols
__global__ void k_pool(const float* __restrict__ x) {
    __shared__ float ps[4][128];
    __shared__ float pm[4][128];
    int b = blockIdx.x;
    int rg = threadIdx.x >> 7, c = threadIdx.x & 127;
    int st = g_gstart[b], en = g_gstart[b + 1];
    float s = 0.f, m = -INFINITY;
    for (int r = st + rg; r < en; r += 4) {
        float v = x[r * HD + c];
        s += v;
        m = fmaxf(m, v);
    }
    ps[rg][c] = s;
    pm[rg][c] = m;
    __syncthreads();
    if (rg == 0) {
        float ss = ps[0][c] + ps[1][c] + ps[2][c] + ps[3][c];
        float mm = fmaxf(fmaxf(pm[0][c], pm[1][c]), fmaxf(pm[2][c], pm[3][c]));
        int cnt = en - st;
        g_pooled[b * 256 + c] = ss / (float)(cnt > 0 ? cnt : 1);
        g_pooled[b * 256 + 128 + c] = mm;
    }
}

// classifier: z=[pooled|g0] (64x264) -> elu01(z@cw1+cb1) -> BN -> @cw2+cb2 -> softmax
__global__ void k_cls(const float* __restrict__ g0,
                      const float* __restrict__ cw1, const float* __restrict__ cb1,
                      const float* __restrict__ cgm, const float* __restrict__ cbt,
                      const float* __restrict__ cw2, const float* __restrict__ cb2,
                      float* __restrict__ out) {
    __shared__ float zrow[8][264];
    __shared__ float h1[64][128];
    __shared__ float lg[64][2];
    int c = threadIdx.x;  // <<<1,128>>>

    for (int r0 = 0; r0 < 64; r0 += 8) {
        for (int idx = c; idx < 8 * 264; idx += 128) {
            int rr = idx / 264, k = idx - rr * 264;
            int r = r0 + rr;
            zrow[rr][k] = (k < 256) ? g_pooled[r * 256 + k] : g0[r * GF + (k - 256)];
        }
        __syncthreads();
        float acc[8];
#pragma unroll
        for (int rr = 0; rr < 8; rr++) acc[rr] = 0.f;
        for (int k = 0; k < 264; ++k) {
            float w = cw1[k * HD + c];
#pragma unroll
            for (int rr = 0; rr < 8; rr++) acc[rr] += zrow[rr][k] * w;
        }
        float bias = cb1[c];
#pragma unroll
        for (int rr = 0; rr < 8; rr++) h1[r0 + rr][c] = elu01(acc[rr] + bias);
        __syncthreads();
    }

    // BatchNorm over 64 rows (biased var), in place
    float s = 0.f, sq = 0.f;
    for (int r = 0; r < 64; r++) {
        float v = h1[r][c];
        s += v;
        sq += v * v;
    }
    float mean = s * (1.f / 64.f);
    float var = sq * (1.f / 64.f) - mean * mean;
    float a = cgm[c] * rsqrtf(var + BN_EPS);
    float bb = cbt[c] - mean * a;
    for (int r = 0; r < 64; r++) h1[r][c] = h1[r][c] * a + bb;
    __syncthreads();

    // logits + softmax (thread -> one (row, class))
    {
        int r = c >> 1, cls = c & 1;
        float l = cb2[cls];
        for (int k = 0; k < 128; k++) l += h1[r][k] * cw2[k * 2 + cls];
        lg[r][cls] = l;
    }
    __syncthreads();
    {
        int r = c >> 1, cls = c & 1;
        float l0 = lg[r][0], l1 = lg[r][1];
        float mx = fmaxf(l0, l1);
        float e0 = expf(l0 - mx), e1 = expf(l1 - mx);
        out[r * 2 + cls] = ((cls == 0) ? e0 : e1) / (e0 + e1);
    }
}

// ---------------- launch ----------------
extern "C" void kernel_launch(void* const* d_in, const int* in_sizes, int n_in,
                              void* d_out, int out_size) {
    const float* h0     = (const float*)d_in[0];
    const float* coord0 = (const float*)d_in[1];
    const float* g0     = (const float*)d_in[2];
    const int*   eidx   = (const int*)  d_in[3];
    const int*   batch  = (const int*)  d_in[4];
    const float* w1_0 = (const float*)d_in[5];
    const float* b1_0 = (const float*)d_in[6];
    const float* gm_0 = (const float*)d_in[7];
    const float* bt_0 = (const float*)d_in[8];
    const float* w2_0 = (const float*)d_in[9];
    const float* b2_0 = (const float*)d_in[10];
    const float* w1_r = (const float*)d_in[11];
    const float* b1_r = (const float*)d_in[12];
    const float* gm_r = (const float*)d_in[13];
    const float* bt_r = (const float*)d_in[14];
    const float* w2_r = (const float*)d_in[15];
    const float* b2_r = (const float*)d_in[16];
    const float* cw1  = (const float*)d_in[17];
    const float* cb1  = (const float*)d_in[18];
    const float* cgm  = (const float*)d_in[19];
    const float* cbt  = (const float*)d_in[20];
    const float* cw2  = (const float*)d_in[21];
    const float* cb2  = (const float*)d_in[22];

    const int* src = eidx;
    const int* dst = eidx + NE;

    float *xa19, *h, *xagg, *xA, *xB;
    cudaGetSymbolAddress((void**)&xa19, g_xa19);
    cudaGetSymbolAddress((void**)&h,    g_h);
    cudaGetSymbolAddress((void**)&xagg, g_xagg);
    cudaGetSymbolAddress((void**)&xA,   g_xA);
    cudaGetSymbolAddress((void**)&xB,   g_xB);

    const int GB = (NN + 63) / 64;  // GEMM grid (M tiles)

    // ---- layer 0 (Fin = 19 padded to 20) ----
    k_concat<<<(NN * F20 + 255) / 256, 256>>>(h0, coord0);
    k_scatter19<<<(NE * 5 + 255) / 256, 256>>>(src, dst);
    k_zerostats<<<1, 256>>>();
    k_gemm<false, true, false><<<GB, 256>>>(xa19, F20, F19, w1_0, b1_0, h);
    k_bncoef<<<1, 128>>>(gm_0, bt_0);
    k_gemm<true, false, true><<<GB, 256>>>(h, HD, HD, w2_0, b2_0, xA);

    // ---- layers 1..2 (Fin = 128) ----
    for (int i = 0; i < 2; i++) {
        const float* xin = (i == 0) ? xA : xB;
        float* xout      = (i == 0) ? xB : xA;
        k_copy4<<<(NN * HD / 4 + 255) / 256, 256>>>((const float4*)xin, (float4*)xagg, NN * HD / 4);
        k_scatterH<<<(NE * 32 + 255) / 256, 256>>>(xin, xagg, src, dst);
        k_zerostats<<<1, 256>>>();
        k_gemm<false, true, false><<<GB, 256>>>(xagg, HD, HD, w1_r + i * HD * HD, b1_r + i * HD, h);
        k_bncoef<<<1, 128>>>(gm_r + i * HD, bt_r + i * HD);
        k_gemm<true, false, true><<<GB, 256>>>(h, HD, HD, w2_r + i * HD * HD, b2_r + i * HD, xout);
    }

    // ---- pooling + classifier ----
    k_bounds<<<(NN + 255) / 256, 256>>>(batch);
    k_pool<<<NB, 512>>>(xA);
    k_cls<<<1, 128>>>(g0, cw1, cb1, cgm, cbt, cw2, cb2, (float*)d_out);
}

// round 4
// speedup vs baseline: 1.6021x; 1.6021x over previous
#include <cuda_runtime.h>
#include <math.h>

#define NN 100000
#define NE 1600000
#define NB 64
#define FI 16
#define HD 128
#define GF 8
#define F19 19
#define F20 20
#define BN_EPS 1e-5f

typedef unsigned long long ull;

// ---------------- scratch (device globals: allocation-free) ----------------
__device__ float g_x19 [NN * F20];
__device__ float g_xa19[NN * F20];
__device__ float g_h   [NN * HD];
__device__ float g_xagg[NN * HD];
__device__ float g_xA  [NN * HD];
__device__ float g_xB  [NN * HD];
__device__ float g_stats[2 * HD];
__device__ float g_coef [2 * HD];
__device__ int   g_gstart[NB + 1];
__device__ float g_pooled[NB * 2 * HD];

// ---------------- helpers ----------------
__device__ __forceinline__ void red_add_v4(float* p, float4 v) {
    asm volatile("red.global.add.v4.f32 [%0], {%1,%2,%3,%4};"
                 :: "l"(p), "f"(v.x), "f"(v.y), "f"(v.z), "f"(v.w) : "memory");
}

__device__ __forceinline__ float elu01(float v) {
    return v > 0.f ? v : 0.1f * expm1f(v);
}

// packed f32x2 FMA (sm_103a packed fp32 pipe; ptxas never auto-fuses this)
__device__ __forceinline__ void ffma2(ull& d, ull a, ull b) {
    asm("fma.rn.f32x2 %0, %1, %2, %0;" : "+l"(d) : "l"(a), "l"(b));
}
__device__ __forceinline__ ull dup2(float a) {
    ull r; asm("mov.b64 %0, {%1, %1};" : "=l"(r) : "f"(a)); return r;
}
__device__ __forceinline__ ull pk2(float x, float y) {
    ull r; asm("mov.b64 %0, {%1, %2};" : "=l"(r) : "f"(x), "f"(y)); return r;
}
__device__ __forceinline__ float2 upk(ull v) {
    float2 f; asm("mov.b64 {%0, %1}, %2;" : "=f"(f.x), "=f"(f.y) : "l"(v)); return f;
}

// ---------------- small kernels ----------------

__global__ void k_concat(const float* __restrict__ h0, const float* __restrict__ coord) {
    int i = blockIdx.x * blockDim.x + threadIdx.x;
    if (i >= NN * F20) return;
    int n = i / F20, j = i - n * F20;
    float v = 0.f;
    if (j < FI)        v = h0[n * FI + j];
    else if (j < F19)  v = coord[n * 3 + (j - FI)];
    g_x19[i] = v;
    g_xa19[i] = v;
}

__global__ void k_scatter19(const int* __restrict__ src, const int* __restrict__ dst) {
    int t = blockIdx.x * blockDim.x + threadIdx.x;
    if (t >= NE * 5) return;
    int e = t / 5, c = (t - e * 5) * 4;
    int s = src[e], d = dst[e];
    float4 v = *(const float4*)&g_x19[s * F20 + c];
    red_add_v4(&g_xa19[d * F20 + c], v);
}

__global__ void k_scatterH(const float* __restrict__ x, float* __restrict__ xa,
                           const int* __restrict__ src, const int* __restrict__ dst) {
    int t = blockIdx.x * blockDim.x + threadIdx.x;
    if (t >= NE * 32) return;
    int e = t >> 5, c = (t & 31) << 2;
    int s = src[e], d = dst[e];
    float4 v = *(const float4*)&x[s * HD + c];
    red_add_v4(&xa[d * HD + c], v);
}

__global__ void k_copy4(const float4* __restrict__ in, float4* __restrict__ out, int n4) {
    int i = blockIdx.x * blockDim.x + threadIdx.x;
    if (i < n4) out[i] = in[i];
}

__global__ void k_zerostats() { g_stats[threadIdx.x] = 0.f; }  // <<<1,256>>>

// ---------------- main GEMM ----------------
// out[M,128] = act(A[M,K]) @ W[K,128] + bias, 128x128 block tile, 256 threads,
// 8x8 microtile per thread using packed fma.rn.f32x2.
//  TRANS_A: A elements get BN scale/shift + relu on load (reads g_coef)
//  STATS  : column sums/sumsq of the biased output accumulated into g_stats
//  ELU    : elu01 on output
template <bool TRANS_A, bool STATS, bool ELU>
__global__ void __launch_bounds__(256, 2)
k_gemm(const float* __restrict__ A, int lda, int K,
       const float* __restrict__ W, const float* __restrict__ bias,
       float* __restrict__ out) {
    __shared__ float As[16 * 128];   // [k][m]
    __shared__ float Bs[16 * 128];   // [k][n]

    const int tid = threadIdx.x;
    const int tx = tid & 15;          // col group (8 cols)
    const int ty = tid >> 4;          // row group (8 rows)
    const int m0 = blockIdx.x * 128;

    ull acc[8][4];
#pragma unroll
    for (int r = 0; r < 8; r++)
#pragma unroll
        for (int c = 0; c < 4; c++) acc[r][c] = 0ull;

    const int nkt = (K + 15) / 16;
    for (int kt = 0; kt < nkt; kt++) {
        const int k0 = kt * 16;
        // ---- load A tile (transposed into As[k][m]) : 2 float4 per thread ----
#pragma unroll
        for (int p = 0; p < 2; p++) {
            int idx = tid * 2 + p;          // 0..511
            int r   = idx >> 2;             // 0..127
            int kq  = idx & 3;              // 0..3
            int gk  = k0 + kq * 4;
            int grow = m0 + r;
            float4 v = make_float4(0.f, 0.f, 0.f, 0.f);
            if (grow < NN && gk < K)
                v = *(const float4*)&A[(size_t)grow * lda + gk];
            if (TRANS_A) {
                float4 ca = *(const float4*)&g_coef[gk];
                float4 cb = *(const float4*)&g_coef[128 + gk];
                v.x = fmaxf(fmaf(ca.x, v.x, cb.x), 0.f);
                v.y = fmaxf(fmaf(ca.y, v.y, cb.y), 0.f);
                v.z = fmaxf(fmaf(ca.z, v.z, cb.z), 0.f);
                v.w = fmaxf(fmaf(ca.w, v.w, cb.w), 0.f);
            }
            As[(gk - k0 + 0) * 128 + r] = v.x;
            As[(gk - k0 + 1) * 128 + r] = v.y;
            As[(gk - k0 + 2) * 128 + r] = v.z;
            As[(gk - k0 + 3) * 128 + r] = v.w;
        }
        // ---- load W tile: 2 float4 per thread ----
#pragma unroll
        for (int p = 0; p < 2; p++) {
            int idx = tid * 2 + p;          // 0..511
            int kk  = idx >> 5;             // 0..15
            int n4  = idx & 31;             // 0..31
            float4 v = make_float4(0.f, 0.f, 0.f, 0.f);
            if (k0 + kk < K)
                v = *(const float4*)&W[(size_t)(k0 + kk) * HD + n4 * 4];
            *(float4*)&Bs[kk * 128 + n4 * 4] = v;
        }
        __syncthreads();

#pragma unroll
        for (int k = 0; k < 16; k++) {
            float4 a0 = *(const float4*)&As[k * 128 + ty * 8];
            float4 a1 = *(const float4*)&As[k * 128 + ty * 8 + 4];
            float4 b0 = *(const float4*)&Bs[k * 128 + tx * 8];
            float4 b1 = *(const float4*)&Bs[k * 128 + tx * 8 + 4];
            ull bp0 = pk2(b0.x, b0.y), bp1 = pk2(b0.z, b0.w);
            ull bp2 = pk2(b1.x, b1.y), bp3 = pk2(b1.z, b1.w);
            float ar[8] = {a0.x, a0.y, a0.z, a0.w, a1.x, a1.y, a1.z, a1.w};
#pragma unroll
            for (int r = 0; r < 8; r++) {
                ull ap = dup2(ar[r]);
                ffma2(acc[r][0], ap, bp0);
                ffma2(acc[r][1], ap, bp1);
                ffma2(acc[r][2], ap, bp2);
                ffma2(acc[r][3], ap, bp3);
            }
        }
        __syncthreads();
    }

    // ---- epilogue ----
    float4 bb0 = *(const float4*)&bias[tx * 8];
    float4 bb1 = *(const float4*)&bias[tx * 8 + 4];
    float bv[8] = {bb0.x, bb0.y, bb0.z, bb0.w, bb1.x, bb1.y, bb1.z, bb1.w};

    float cS[8], cQ[8];
    if (STATS) {
#pragma unroll
        for (int c = 0; c < 8; c++) { cS[c] = 0.f; cQ[c] = 0.f; }
    }

#pragma unroll
    for (int r = 0; r < 8; r++) {
        int grow = m0 + ty * 8 + r;
        if (grow < NN) {
            float2 p0 = upk(acc[r][0]), p1 = upk(acc[r][1]);
            float2 p2 = upk(acc[r][2]), p3 = upk(acc[r][3]);
            float v[8] = {p0.x, p0.y, p1.x, p1.y, p2.x, p2.y, p3.x, p3.y};
#pragma unroll
            for (int c = 0; c < 8; c++) {
                v[c] += bv[c];
                if (STATS) { cS[c] += v[c]; cQ[c] += v[c] * v[c]; }
                if (ELU) v[c] = elu01(v[c]);
            }
            float4 o0 = make_float4(v[0], v[1], v[2], v[3]);
            float4 o1 = make_float4(v[4], v[5], v[6], v[7]);
            *(float4*)&out[(size_t)grow * HD + tx * 8] = o0;
            *(float4*)&out[(size_t)grow * HD + tx * 8 + 4] = o1;
        }
    }

    if (STATS) {
        // tree-reduce per-thread column partials through As scratch (16x128)
        __syncthreads();
#pragma unroll
        for (int c = 0; c < 8; c++) As[ty * 128 + tx * 8 + c] = cS[c];
        __syncthreads();
        if (tid < 128) {
            float s = 0.f;
#pragma unroll
            for (int j = 0; j < 16; j++) s += As[j * 128 + tid];
            atomicAdd(&g_stats[tid], s);
        }
        __syncthreads();
#pragma unroll
        for (int c = 0; c < 8; c++) As[ty * 128 + tx * 8 + c] = cQ[c];
        __syncthreads();
        if (tid < 128) {
            float s = 0.f;
#pragma unroll
            for (int j = 0; j < 16; j++) s += As[j * 128 + tid];
            atomicAdd(&g_stats[128 + tid], s);
        }
    }
}

// ---------------- BN coef / pooling / classifier ----------------

__global__ void k_bncoef(const float* __restrict__ gm, const float* __restrict__ bt) {
    int c = threadIdx.x;  // <<<1,128>>>
    float mean = g_stats[c] * (1.f / NN);
    float var = g_stats[128 + c] * (1.f / NN) - mean * mean;
    float a = gm[c] * rsqrtf(var + BN_EPS);
    g_coef[c] = a;
    g_coef[128 + c] = bt[c] - mean * a;
}

__global__ void k_bounds(const int* __restrict__ batch) {
    int i = blockIdx.x * blockDim.x + threadIdx.x;
    if (i >= NN) return;
    int cur = batch[i];
    int prev = (i == 0) ? -1 : batch[i - 1];
    for (int g = prev + 1; g <= cur; ++g) g_gstart[g] = i;
    if (i == NN - 1)
        for (int g = cur + 1; g <= NB; ++g) g_gstart[g] = NN;
}

__global__ void k_pool(const float* __restrict__ x) {
    __shared__ float ps[4][128];
    __shared__ float pm[4][128];
    int b = blockIdx.x;
    int rg = threadIdx.x >> 7, c = threadIdx.x & 127;
    int st = g_gstart[b], en = g_gstart[b + 1];
    float s = 0.f, m = -INFINITY;
    for (int r = st + rg; r < en; r += 4) {
        float v = x[r * HD + c];
        s += v;
        m = fmaxf(m, v);
    }
    ps[rg][c] = s;
    pm[rg][c] = m;
    __syncthreads();
    if (rg == 0) {
        float ss = ps[0][c] + ps[1][c] + ps[2][c] + ps[3][c];
        float mm = fmaxf(fmaxf(pm[0][c], pm[1][c]), fmaxf(pm[2][c], pm[3][c]));
        int cnt = en - st;
        g_pooled[b * 256 + c] = ss / (float)(cnt > 0 ? cnt : 1);
        g_pooled[b * 256 + 128 + c] = mm;
    }
}

__global__ void k_cls(const float* __restrict__ g0,
                      const float* __restrict__ cw1, const float* __restrict__ cb1,
                      const float* __restrict__ cgm, const float* __restrict__ cbt,
                      const float* __restrict__ cw2, const float* __restrict__ cb2,
                      float* __restrict__ out) {
    __shared__ float zrow[8][264];
    __shared__ float h1[64][128];
    __shared__ float lg[64][2];
    int c = threadIdx.x;  // <<<1,128>>>

    for (int r0 = 0; r0 < 64; r0 += 8) {
        for (int idx = c; idx < 8 * 264; idx += 128) {
            int rr = idx / 264, k = idx - rr * 264;
            int r = r0 + rr;
            zrow[rr][k] = (k < 256) ? g_pooled[r * 256 + k] : g0[r * GF + (k - 256)];
        }
        __syncthreads();
        float acc[8];
#pragma unroll
        for (int rr = 0; rr < 8; rr++) acc[rr] = 0.f;
        for (int k = 0; k < 264; ++k) {
            float w = cw1[k * HD + c];
#pragma unroll
            for (int rr = 0; rr < 8; rr++) acc[rr] += zrow[rr][k] * w;
        }
        float bias = cb1[c];
#pragma unroll
        for (int rr = 0; rr < 8; rr++) h1[r0 + rr][c] = elu01(acc[rr] + bias);
        __syncthreads();
    }

    float s = 0.f, sq = 0.f;
    for (int r = 0; r < 64; r++) {
        float v = h1[r][c];
        s += v;
        sq += v * v;
    }
    float mean = s * (1.f / 64.f);
    float var = sq * (1.f / 64.f) - mean * mean;
    float a = cgm[c] * rsqrtf(var + BN_EPS);
    float bb = cbt[c] - mean * a;
    for (int r = 0; r < 64; r++) h1[r][c] = h1[r][c] * a + bb;
    __syncthreads();

    {
        int r = c >> 1, cls = c & 1;
        float l = cb2[cls];
        for (int k = 0; k < 128; k++) l += h1[r][k] * cw2[k * 2 + cls];
        lg[r][cls] = l;
    }
    __syncthreads();
    {
        int r = c >> 1, cls = c & 1;
        float l0 = lg[r][0], l1 = lg[r][1];
        float mx = fmaxf(l0, l1);
        float e0 = expf(l0 - mx), e1 = expf(l1 - mx);
        out[r * 2 + cls] = ((cls == 0) ? e0 : e1) / (e0 + e1);
    }
}

// ---------------- launch ----------------
extern "C" void kernel_launch(void* const* d_in, const int* in_sizes, int n_in,
                              void* d_out, int out_size) {
    const float* h0     = (const float*)d_in[0];
    const float* coord0 = (const float*)d_in[1];
    const float* g0     = (const float*)d_in[2];
    const int*   eidx   = (const int*)  d_in[3];
    const int*   batch  = (const int*)  d_in[4];
    const float* w1_0 = (const float*)d_in[5];
    const float* b1_0 = (const float*)d_in[6];
    const float* gm_0 = (const float*)d_in[7];
    const float* bt_0 = (const float*)d_in[8];
    const float* w2_0 = (const float*)d_in[9];
    const float* b2_0 = (const float*)d_in[10];
    const float* w1_r = (const float*)d_in[11];
    const float* b1_r = (const float*)d_in[12];
    const float* gm_r = (const float*)d_in[13];
    const float* bt_r = (const float*)d_in[14];
    const float* w2_r = (const float*)d_in[15];
    const float* b2_r = (const float*)d_in[16];
    const float* cw1  = (const float*)d_in[17];
    const float* cb1  = (const float*)d_in[18];
    const float* cgm  = (const float*)d_in[19];
    const float* cbt  = (const float*)d_in[20];
    const float* cw2  = (const float*)d_in[21];
    const float* cb2  = (const float*)d_in[22];

    const int* src = eidx;
    const int* dst = eidx + NE;

    float *xa19, *h, *xagg, *xA, *xB;
    cudaGetSymbolAddress((void**)&xa19, g_xa19);
    cudaGetSymbolAddress((void**)&h,    g_h);
    cudaGetSymbolAddress((void**)&xagg, g_xagg);
    cudaGetSymbolAddress((void**)&xA,   g_xA);
    cudaGetSymbolAddress((void**)&xB,   g_xB);

    const int GB = (NN + 127) / 128;  // GEMM grid (M tiles)

    // ---- layer 0 (Fin = 19 padded to 20) ----
    k_concat<<<(NN * F20 + 255) / 256, 256>>>(h0, coord0);
    k_scatter19<<<(NE * 5 + 255) / 256, 256>>>(src, dst);
    k_zerostats<<<1, 256>>>();
    k_gemm<false, true, false><<<GB, 256>>>(xa19, F20, F19, w1_0, b1_0, h);
    k_bncoef<<<1, 128>>>(gm_0, bt_0);
    k_gemm<true, false, true><<<GB, 256>>>(h, HD, HD, w2_0, b2_0, xA);

    // ---- layers 1..2 (Fin = 128) ----
    for (int i = 0; i < 2; i++) {
        const float* xin = (i == 0) ? xA : xB;
        float* xout      = (i == 0) ? xB : xA;
        k_copy4<<<(NN * HD / 4 + 255) / 256, 256>>>((const float4*)xin, (float4*)xagg, NN * HD / 4);
        k_scatterH<<<(NE * 32 + 255) / 256, 256>>>(xin, xagg, src, dst);
        k_zerostats<<<1, 256>>>();
        k_gemm<false, true, false><<<GB, 256>>>(xagg, HD, HD, w1_r + i * HD * HD, b1_r + i * HD, h);
        k_bncoef<<<1, 128>>>(gm_r + i * HD, bt_r + i * HD);
        k_gemm<true, false, true><<<GB, 256>>>(h, HD, HD, w2_r + i * HD * HD, b2_r + i * HD, xout);
    }

    // ---- pooling + classifier ----
    k_bounds<<<(NN + 255) / 256, 256>>>(batch);
    k_pool<<<NB, 512>>>(xA);
    k_cls<<<1, 128>>>(g0, cw1, cb1, cgm, cbt, cw2, cb2, (float*)d_out);
}

// round 5
// speedup vs baseline: 2.0323x; 1.2685x over previous
#include <cuda_runtime.h>
#include <math.h>

#define NN 100000
#define NE 1600000
#define NB 64
#define FI 16
#define HD 128
#define GF 8
#define F19 19
#define F20 20
#define BN_EPS 1e-5f
#define SCAN_BS 1024
#define SCAN_NBLK ((NN + SCAN_BS - 1) / SCAN_BS)   // 98

typedef unsigned long long ull;

// ---------------- scratch (device globals: allocation-free) ----------------
__device__ float g_x19 [NN * F20];
__device__ float g_xa19[NN * F20];
__device__ float g_h   [NN * HD];
__device__ float g_xagg[NN * HD];
__device__ float g_xA  [NN * HD];
__device__ float g_xB  [NN * HD];
__device__ float g_stats[2 * HD];
__device__ float g_coef [2 * HD];
__device__ int   g_gstart[NB + 1];
__device__ float g_pooled[NB * 2 * HD];
// CSR scratch
__device__ int g_deg[NN];
__device__ int g_rowstart[NN + 1];
__device__ int g_cursor[NN];
__device__ int g_esrc[NE];
__device__ int g_bsum[SCAN_NBLK];

// ---------------- helpers ----------------
__device__ __forceinline__ float elu01(float v) {
    return v > 0.f ? v : 0.1f * expm1f(v);
}
// packed f32x2 FMA (sm_103a; ptxas never auto-fuses this)
__device__ __forceinline__ void ffma2(ull& d, ull a, ull b) {
    asm("fma.rn.f32x2 %0, %1, %2, %0;" : "+l"(d) : "l"(a), "l"(b));
}
__device__ __forceinline__ ull dup2(float a) {
    ull r; asm("mov.b64 %0, {%1, %1};" : "=l"(r) : "f"(a)); return r;
}
__device__ __forceinline__ ull pk2(float x, float y) {
    ull r; asm("mov.b64 %0, {%1, %2};" : "=l"(r) : "f"(x), "f"(y)); return r;
}
__device__ __forceinline__ float2 upk(ull v) {
    float2 f; asm("mov.b64 {%0, %1}, %2;" : "=f"(f.x), "=f"(f.y) : "l"(v)); return f;
}

// ---------------- CSR build ----------------
__global__ void k_zerodeg() {
    int i = blockIdx.x * blockDim.x + threadIdx.x;
    if (i < NN) g_deg[i] = 0;
}
__global__ void k_deg(const int* __restrict__ dst) {
    int e = blockIdx.x * blockDim.x + threadIdx.x;
    if (e < NE) atomicAdd(&g_deg[dst[e]], 1);
}
// block-level inclusive scan -> exclusive rowstart (partial) + block sums
__global__ void k_scanA() {
    __shared__ int s[SCAN_BS];
    int i = blockIdx.x * SCAN_BS + threadIdx.x;
    int v = (i < NN) ? g_deg[i] : 0;
    s[threadIdx.x] = v;
    __syncthreads();
#pragma unroll
    for (int off = 1; off < SCAN_BS; off <<= 1) {
        int t = (threadIdx.x >= off) ? s[threadIdx.x - off] : 0;
        __syncthreads();
        s[threadIdx.x] += t;
        __syncthreads();
    }
    if (i < NN) g_rowstart[i] = s[threadIdx.x] - v;   // exclusive within block
    if (threadIdx.x == SCAN_BS - 1) g_bsum[blockIdx.x] = s[SCAN_BS - 1];
}
__global__ void k_scanB() {   // <<<1,1>>> serial scan of 98 block sums
    int acc = 0;
    for (int b = 0; b < SCAN_NBLK; b++) {
        int t = g_bsum[b];
        g_bsum[b] = acc;
        acc += t;
    }
    g_rowstart[NN] = NE;
}
__global__ void k_scanC() {
    int i = blockIdx.x * blockDim.x + threadIdx.x;
    if (i < NN) {
        int r = g_rowstart[i] + g_bsum[i / SCAN_BS];
        g_rowstart[i] = r;
        g_cursor[i] = r;
    }
}
__global__ void k_fill(const int* __restrict__ src, const int* __restrict__ dst) {
    int e = blockIdx.x * blockDim.x + threadIdx.x;
    if (e < NE) {
        int pos = atomicAdd(&g_cursor[dst[e]], 1);
        g_esrc[pos] = src[e];
    }
}

// ---------------- feature prep + gather aggregation ----------------
__global__ void k_concat(const float* __restrict__ h0, const float* __restrict__ coord) {
    int i = blockIdx.x * blockDim.x + threadIdx.x;
    if (i >= NN * F20) return;
    int n = i / F20, j = i - n * F20;
    float v = 0.f;
    if (j < FI)        v = h0[n * FI + j];
    else if (j < F19)  v = coord[n * 3 + (j - FI)];
    g_x19[i] = v;
}

// warp per node; lanes 0..4 each own 4 of the 20 cols
__global__ void k_gather19() {
    int node = blockIdx.x * 8 + (threadIdx.x >> 5);
    int lane = threadIdx.x & 31;
    if (node >= NN || lane >= 5) return;
    int st = g_rowstart[node], en = g_rowstart[node + 1];
    float4 v = *(const float4*)&g_x19[node * F20 + lane * 4];
    for (int e = st; e < en; e++) {
        int s = g_esrc[e];
        float4 u = *(const float4*)&g_x19[s * F20 + lane * 4];
        v.x += u.x; v.y += u.y; v.z += u.z; v.w += u.w;
    }
    *(float4*)&g_xa19[node * F20 + lane * 4] = v;
}

// warp per node; lane owns cols 4*lane..4*lane+3 of 128
__global__ void k_gatherH(const float* __restrict__ x, float* __restrict__ xa) {
    int node = blockIdx.x * 8 + (threadIdx.x >> 5);
    if (node >= NN) return;
    int lane = threadIdx.x & 31;
    int st = g_rowstart[node], en = g_rowstart[node + 1];
    float4 v = *(const float4*)&x[(size_t)node * HD + lane * 4];
    for (int e = st; e < en; e++) {
        int s = g_esrc[e];
        float4 u = *(const float4*)&x[(size_t)s * HD + lane * 4];
        v.x += u.x; v.y += u.y; v.z += u.z; v.w += u.w;
    }
    *(float4*)&xa[(size_t)node * HD + lane * 4] = v;
}

__global__ void k_zerostats() { g_stats[threadIdx.x] = 0.f; }  // <<<1,256>>>

// ---------------- main GEMM (ping-pong smem + register prefetch) ----------------
__device__ __forceinline__ void ld_tiles(const float* __restrict__ A, int lda, int K,
                                         const float* __restrict__ W,
                                         int m0, int k0, int tid,
                                         float4* pa, float4* pw) {
#pragma unroll
    for (int p = 0; p < 2; p++) {
        int idx = tid * 2 + p;
        int r = idx >> 2, kq = idx & 3;
        int gk = k0 + kq * 4, grow = m0 + r;
        float4 v = make_float4(0.f, 0.f, 0.f, 0.f);
        if (grow < NN && gk < K) v = *(const float4*)&A[(size_t)grow * lda + gk];
        pa[p] = v;
        int kk = idx >> 5, n4 = idx & 31;
        float4 w = make_float4(0.f, 0.f, 0.f, 0.f);
        if (k0 + kk < K) w = *(const float4*)&W[(size_t)(k0 + kk) * HD + n4 * 4];
        pw[p] = w;
    }
}

template <bool TRANS_A>
__device__ __forceinline__ void st_tiles(float* __restrict__ As, float* __restrict__ Bs,
                                         int k0, int tid,
                                         const float4* pa, const float4* pw) {
#pragma unroll
    for (int p = 0; p < 2; p++) {
        int idx = tid * 2 + p;
        int r = idx >> 2, kq = idx & 3;
        float4 v = pa[p];
        if (TRANS_A) {
            int gk = k0 + kq * 4;   // TRANS_A only used with K=128
            float4 ca = *(const float4*)&g_coef[gk];
            float4 cb = *(const float4*)&g_coef[128 + gk];
            v.x = fmaxf(fmaf(ca.x, v.x, cb.x), 0.f);
            v.y = fmaxf(fmaf(ca.y, v.y, cb.y), 0.f);
            v.z = fmaxf(fmaf(ca.z, v.z, cb.z), 0.f);
            v.w = fmaxf(fmaf(ca.w, v.w, cb.w), 0.f);
        }
        As[(kq * 4 + 0) * 128 + r] = v.x;
        As[(kq * 4 + 1) * 128 + r] = v.y;
        As[(kq * 4 + 2) * 128 + r] = v.z;
        As[(kq * 4 + 3) * 128 + r] = v.w;
        int kk = idx >> 5, n4 = idx & 31;
        *(float4*)&Bs[kk * 128 + n4 * 4] = pw[p];
    }
}

// out[M,128] = act(A[M,K]) @ W[K,128] + bias; 128x128 tile, 256 thr, 8x8 microtile, FFMA2
template <bool TRANS_A, bool STATS, bool ELU>
__global__ void __launch_bounds__(256, 2)
k_gemm(const float* __restrict__ A, int lda, int K,
       const float* __restrict__ W, const float* __restrict__ bias,
       float* __restrict__ out) {
    __shared__ float As[2][16 * 128];
    __shared__ float Bs[2][16 * 128];

    const int tid = threadIdx.x;
    const int tx = tid & 15;
    const int ty = tid >> 4;
    const int m0 = blockIdx.x * 128;

    ull acc[8][4];
#pragma unroll
    for (int r = 0; r < 8; r++)
#pragma unroll
        for (int c = 0; c < 4; c++) acc[r][c] = 0ull;

    const int nkt = (K + 15) / 16;
    float4 pa[2], pw[2];

    ld_tiles(A, lda, K, W, m0, 0, tid, pa, pw);
    st_tiles<TRANS_A>(As[0], Bs[0], 0, tid, pa, pw);
    __syncthreads();

    for (int kt = 0; kt < nkt; kt++) {
        const float* Ac = As[kt & 1];
        const float* Bc = Bs[kt & 1];
        if (kt + 1 < nkt)
            ld_tiles(A, lda, K, W, m0, (kt + 1) * 16, tid, pa, pw);
#pragma unroll
        for (int k = 0; k < 16; k++) {
            float4 a0 = *(const float4*)&Ac[k * 128 + ty * 8];
            float4 a1 = *(const float4*)&Ac[k * 128 + ty * 8 + 4];
            float4 b0 = *(const float4*)&Bc[k * 128 + tx * 8];
            float4 b1 = *(const float4*)&Bc[k * 128 + tx * 8 + 4];
            ull bp0 = pk2(b0.x, b0.y), bp1 = pk2(b0.z, b0.w);
            ull bp2 = pk2(b1.x, b1.y), bp3 = pk2(b1.z, b1.w);
            float ar[8] = {a0.x, a0.y, a0.z, a0.w, a1.x, a1.y, a1.z, a1.w};
#pragma unroll
            for (int r = 0; r < 8; r++) {
                ull ap = dup2(ar[r]);
                ffma2(acc[r][0], ap, bp0);
                ffma2(acc[r][1], ap, bp1);
                ffma2(acc[r][2], ap, bp2);
                ffma2(acc[r][3], ap, bp3);
            }
        }
        if (kt + 1 < nkt)
            st_tiles<TRANS_A>(As[(kt + 1) & 1], Bs[(kt + 1) & 1], (kt + 1) * 16, tid, pa, pw);
        __syncthreads();
    }

    // ---- epilogue ----
    float4 bb0 = *(const float4*)&bias[tx * 8];
    float4 bb1 = *(const float4*)&bias[tx * 8 + 4];
    float bv[8] = {bb0.x, bb0.y, bb0.z, bb0.w, bb1.x, bb1.y, bb1.z, bb1.w};

    float cS[8], cQ[8];
    if (STATS) {
#pragma unroll
        for (int c = 0; c < 8; c++) { cS[c] = 0.f; cQ[c] = 0.f; }
    }

#pragma unroll
    for (int r = 0; r < 8; r++) {
        int grow = m0 + ty * 8 + r;
        if (grow < NN) {
            float2 p0 = upk(acc[r][0]), p1 = upk(acc[r][1]);
            float2 p2 = upk(acc[r][2]), p3 = upk(acc[r][3]);
            float v[8] = {p0.x, p0.y, p1.x, p1.y, p2.x, p2.y, p3.x, p3.y};
#pragma unroll
            for (int c = 0; c < 8; c++) {
                v[c] += bv[c];
                if (STATS) { cS[c] += v[c]; cQ[c] += v[c] * v[c]; }
                if (ELU) v[c] = elu01(v[c]);
            }
            *(float4*)&out[(size_t)grow * HD + tx * 8]     = make_float4(v[0], v[1], v[2], v[3]);
            *(float4*)&out[(size_t)grow * HD + tx * 8 + 4] = make_float4(v[4], v[5], v[6], v[7]);
        }
    }

    if (STATS) {
        float* scr = As[0];
        __syncthreads();
#pragma unroll
        for (int c = 0; c < 8; c++) scr[ty * 128 + tx * 8 + c] = cS[c];
        __syncthreads();
        if (tid < 128) {
            float s = 0.f;
#pragma unroll
            for (int j = 0; j < 16; j++) s += scr[j * 128 + tid];
            atomicAdd(&g_stats[tid], s);
        }
        __syncthreads();
#pragma unroll
        for (int c = 0; c < 8; c++) scr[ty * 128 + tx * 8 + c] = cQ[c];
        __syncthreads();
        if (tid < 128) {
            float s = 0.f;
#pragma unroll
            for (int j = 0; j < 16; j++) s += scr[j * 128 + tid];
            atomicAdd(&g_stats[128 + tid], s);
        }
    }
}

// ---------------- BN coef / pooling / classifier ----------------
__global__ void k_bncoef(const float* __restrict__ gm, const float* __restrict__ bt) {
    int c = threadIdx.x;  // <<<1,128>>>
    float mean = g_stats[c] * (1.f / NN);
    float var = g_stats[128 + c] * (1.f / NN) - mean * mean;
    float a = gm[c] * rsqrtf(var + BN_EPS);
    g_coef[c] = a;
    g_coef[128 + c] = bt[c] - mean * a;
}

__global__ void k_bounds(const int* __restrict__ batch) {
    int i = blockIdx.x * blockDim.x + threadIdx.x;
    if (i >= NN) return;
    int cur = batch[i];
    int prev = (i == 0) ? -1 : batch[i - 1];
    for (int g = prev + 1; g <= cur; ++g) g_gstart[g] = i;
    if (i == NN - 1)
        for (int g = cur + 1; g <= NB; ++g) g_gstart[g] = NN;
}

__global__ void k_pool(const float* __restrict__ x) {
    __shared__ float ps[4][128];
    __shared__ float pm[4][128];
    int b = blockIdx.x;
    int rg = threadIdx.x >> 7, c = threadIdx.x & 127;
    int st = g_gstart[b], en = g_gstart[b + 1];
    float s = 0.f, m = -INFINITY;
    for (int r = st + rg; r < en; r += 4) {
        float v = x[(size_t)r * HD + c];
        s += v;
        m = fmaxf(m, v);
    }
    ps[rg][c] = s;
    pm[rg][c] = m;
    __syncthreads();
    if (rg == 0) {
        float ss = ps[0][c] + ps[1][c] + ps[2][c] + ps[3][c];
        float mm = fmaxf(fmaxf(pm[0][c], pm[1][c]), fmaxf(pm[2][c], pm[3][c]));
        int cnt = en - st;
        g_pooled[b * 256 + c] = ss / (float)(cnt > 0 ? cnt : 1);
        g_pooled[b * 256 + 128 + c] = mm;
    }
}

__global__ void k_cls(const float* __restrict__ g0,
                      const float* __restrict__ cw1, const float* __restrict__ cb1,
                      const float* __restrict__ cgm, const float* __restrict__ cbt,
                      const float* __restrict__ cw2, const float* __restrict__ cb2,
                      float* __restrict__ out) {
    __shared__ float zrow[8][264];
    __shared__ float h1[64][128];
    __shared__ float lg[64][2];
    int c = threadIdx.x;  // <<<1,128>>>

    for (int r0 = 0; r0 < 64; r0 += 8) {
        for (int idx = c; idx < 8 * 264; idx += 128) {
            int rr = idx / 264, k = idx - rr * 264;
            int r = r0 + rr;
            zrow[rr][k] = (k < 256) ? g_pooled[r * 256 + k] : g0[r * GF + (k - 256)];
        }
        __syncthreads();
        float acc[8];
#pragma unroll
        for (int rr = 0; rr < 8; rr++) acc[rr] = 0.f;
        for (int k = 0; k < 264; ++k) {
            float w = cw1[k * HD + c];
#pragma unroll
            for (int rr = 0; rr < 8; rr++) acc[rr] += zrow[rr][k] * w;
        }
        float bias = cb1[c];
#pragma unroll
        for (int rr = 0; rr < 8; rr++) h1[r0 + rr][c] = elu01(acc[rr] + bias);
        __syncthreads();
    }

    float s = 0.f, sq = 0.f;
    for (int r = 0; r < 64; r++) {
        float v = h1[r][c];
        s += v;
        sq += v * v;
    }
    float mean = s * (1.f / 64.f);
    float var = sq * (1.f / 64.f) - mean * mean;
    float a = cgm[c] * rsqrtf(var + BN_EPS);
    float bb = cbt[c] - mean * a;
    for (int r = 0; r < 64; r++) h1[r][c] = h1[r][c] * a + bb;
    __syncthreads();

    {
        int r = c >> 1, cls = c & 1;
        float l = cb2[cls];
        for (int k = 0; k < 128; k++) l += h1[r][k] * cw2[k * 2 + cls];
        lg[r][cls] = l;
    }
    __syncthreads();
    {
        int r = c >> 1, cls = c & 1;
        float l0 = lg[r][0], l1 = lg[r][1];
        float mx = fmaxf(l0, l1);
        float e0 = expf(l0 - mx), e1 = expf(l1 - mx);
        out[r * 2 + cls] = ((cls == 0) ? e0 : e1) / (e0 + e1);
    }
}

// ---------------- launch ----------------
extern "C" void kernel_launch(void* const* d_in, const int* in_sizes, int n_in,
                              void* d_out, int out_size) {
    const float* h0     = (const float*)d_in[0];
    const float* coord0 = (const float*)d_in[1];
    const float* g0     = (const float*)d_in[2];
    const int*   eidx   = (const int*)  d_in[3];
    const int*   batch  = (const int*)  d_in[4];
    const float* w1_0 = (const float*)d_in[5];
    const float* b1_0 = (const float*)d_in[6];
    const float* gm_0 = (const float*)d_in[7];
    const float* bt_0 = (const float*)d_in[8];
    const float* w2_0 = (const float*)d_in[9];
    const float* b2_0 = (const float*)d_in[10];
    const float* w1_r = (const float*)d_in[11];
    const float* b1_r = (const float*)d_in[12];
    const float* gm_r = (const float*)d_in[13];
    const float* bt_r = (const float*)d_in[14];
    const float* w2_r = (const float*)d_in[15];
    const float* b2_r = (const float*)d_in[16];
    const float* cw1  = (const float*)d_in[17];
    const float* cb1  = (const float*)d_in[18];
    const float* cgm  = (const float*)d_in[19];
    const float* cbt  = (const float*)d_in[20];
    const float* cw2  = (const float*)d_in[21];
    const float* cb2  = (const float*)d_in[22];

    const int* src = eidx;
    const int* dst = eidx + NE;

    float *xa19, *h, *xagg, *xA, *xB;
    cudaGetSymbolAddress((void**)&xa19, g_xa19);
    cudaGetSymbolAddress((void**)&h,    g_h);
    cudaGetSymbolAddress((void**)&xagg, g_xagg);
    cudaGetSymbolAddress((void**)&xA,   g_xA);
    cudaGetSymbolAddress((void**)&xB,   g_xB);

    const int GB = (NN + 127) / 128;

    // ---- CSR build (dst-sorted edge list) ----
    k_zerodeg<<<(NN + 255) / 256, 256>>>();
    k_deg<<<(NE + 255) / 256, 256>>>(dst);
    k_scanA<<<SCAN_NBLK, SCAN_BS>>>();
    k_scanB<<<1, 1>>>();
    k_scanC<<<(NN + 255) / 256, 256>>>();
    k_fill<<<(NE + 255) / 256, 256>>>(src, dst);

    // ---- layer 0 (Fin = 19 padded to 20) ----
    k_concat<<<(NN * F20 + 255) / 256, 256>>>(h0, coord0);
    k_gather19<<<(NN + 7) / 8, 256>>>();
    k_zerostats<<<1, 256>>>();
    k_gemm<false, true, false><<<GB, 256>>>(xa19, F20, F19, w1_0, b1_0, h);
    k_bncoef<<<1, 128>>>(gm_0, bt_0);
    k_gemm<true, false, true><<<GB, 256>>>(h, HD, HD, w2_0, b2_0, xA);

    // ---- layers 1..2 (Fin = 128) ----
    for (int i = 0; i < 2; i++) {
        const float* xin = (i == 0) ? xA : xB;
        float* xout      = (i == 0) ? xB : xA;
        k_gatherH<<<(NN + 7) / 8, 256>>>(xin, xagg);
        k_zerostats<<<1, 256>>>();
        k_gemm<false, true, false><<<GB, 256>>>(xagg, HD, HD, w1_r + i * HD * HD, b1_r + i * HD, h);
        k_bncoef<<<1, 128>>>(gm_r + i * HD, bt_r + i * HD);
        k_gemm<true, false, true><<<GB, 256>>>(h, HD, HD, w2_r + i * HD * HD, b2_r + i * HD, xout);
    }

    // ---- pooling + classifier ----
    k_bounds<<<(NN + 255) / 256, 256>>>(batch);
    k_pool<<<NB, 512>>>(xA);
    k_cls<<<1, 128>>>(g0, cw1, cb1, cgm, cbt, cw2, cb2, (float*)d_out);
}